// round 9
// baseline (speedup 1.0000x reference)
#include <cuda_runtime.h>
#include <cuda_bf16.h>
#include <cstdint>

// Batched exp of log-affine matrices (ndims=3), B=1e6.
// R9 = R8 (TMA bulk in/out, packed f32x2, two matrices/thread, s=1 deg-4
// Taylor + 1 squaring) + occupancy fix: __launch_bounds__(128,8) caps regs
// at 64 -> 8 CTAs/SM (R8 ran at 80 regs / 30% occ, latency-bound), and
// drop the A^3 t phi1 term (~1e-6 aggregate contribution; budget is 1e-3).

#define TPB 128
#define MPB (2 * TPB)  // matrices per block

typedef unsigned long long u64;

__device__ __forceinline__ uint32_t smem_u32(const void* p) {
    return (uint32_t)__cvta_generic_to_shared(p);
}

__device__ __forceinline__ u64 pk(float lo, float hi) {
    u64 r;
    asm("mov.b64 %0, {%1, %2};" : "=l"(r) : "f"(lo), "f"(hi));
    return r;
}
__device__ __forceinline__ void upk(u64 v, float& lo, float& hi) {
    asm("mov.b64 {%0, %1}, %2;" : "=f"(lo), "=f"(hi) : "l"(v));
}
__device__ __forceinline__ u64 ffma2(u64 a, u64 b, u64 c) {
    u64 d;
    asm("fma.rn.f32x2 %0, %1, %2, %3;" : "=l"(d) : "l"(a), "l"(b), "l"(c));
    return d;
}
__device__ __forceinline__ u64 fmul2(u64 a, u64 b) {
    u64 d;
    asm("mul.rn.f32x2 %0, %1, %2;" : "=l"(d) : "l"(a), "l"(b));
    return d;
}
__device__ __forceinline__ u64 fadd2(u64 a, u64 b) {
    u64 d;
    asm("add.rn.f32x2 %0, %1, %2;" : "=l"(d) : "l"(a), "l"(b));
    return d;
}

// Z = X * Y, 3x3 packed pairs
__device__ __forceinline__ void mm33p(const u64* __restrict__ X,
                                      const u64* __restrict__ Y,
                                      u64* __restrict__ Z) {
#pragma unroll
    for (int r = 0; r < 3; r++) {
        const u64 x0 = X[r * 3 + 0], x1 = X[r * 3 + 1], x2 = X[r * 3 + 2];
#pragma unroll
        for (int c = 0; c < 3; c++)
            Z[r * 3 + c] = ffma2(x0, Y[c], ffma2(x1, Y[3 + c], fmul2(x2, Y[6 + c])));
    }
}

__device__ __forceinline__ void mv3p(const u64* __restrict__ X,
                                     const u64* __restrict__ v,
                                     u64* __restrict__ w) {
#pragma unroll
    for (int r = 0; r < 3; r++)
        w[r] = ffma2(X[r * 3 + 0], v[0],
               ffma2(X[r * 3 + 1], v[1], fmul2(X[r * 3 + 2], v[2])));
}

__global__ void __launch_bounds__(TPB, 8)
expaff_kernel(const float4* __restrict__ in, float4* __restrict__ out, int n) {
    __shared__ alignas(16) float4 s_in[MPB * 3];
    __shared__ alignas(16) float4 s_out[MPB * 3];
    __shared__ alignas(8) unsigned long long mbar;

    const int tid = threadIdx.x;
    const int base = blockIdx.x * MPB;
    const int nblk = min(MPB, n - base);
    const uint32_t bytes = (uint32_t)nblk * 48u;

    const uint32_t mbar_a = smem_u32(&mbar);
    const uint32_t sin_a = smem_u32(s_in);
    const uint32_t sout_a = smem_u32(s_out);

    if (tid == 0) {
        asm volatile("mbarrier.init.shared.b64 [%0], 1;" :: "r"(mbar_a) : "memory");
    }
    __syncthreads();

    if (tid == 0) {
        asm volatile("mbarrier.arrive.expect_tx.shared.b64 _, [%0], %1;"
                     :: "r"(mbar_a), "r"(bytes) : "memory");
        asm volatile(
            "cp.async.bulk.shared::cta.global.mbarrier::complete_tx::bytes "
            "[%0], [%1], %2, [%3];"
            :: "r"(sin_a), "l"(in + (size_t)base * 3), "r"(bytes), "r"(mbar_a)
            : "memory");
    }

    // Wait for TMA load (parity 0)
    {
        uint32_t done;
        asm volatile(
            "{\n\t.reg .pred p;\n\t"
            "mbarrier.try_wait.parity.acquire.cta.shared::cta.b64 p, [%1], 0;\n\t"
            "selp.b32 %0, 1, 0, p;\n\t}"
            : "=r"(done) : "r"(mbar_a) : "memory");
        if (!done) {
            asm volatile(
                "{\n\t.reg .pred P1;\n\t"
                "WL_%=:\n\t"
                "mbarrier.try_wait.parity.acquire.cta.shared::cta.b64 P1, [%0], 0, 0x989680;\n\t"
                "@P1 bra.uni WD_%=;\n\t"
                "bra.uni WL_%=;\n\t"
                "WD_%=:\n\t}"
                :: "r"(mbar_a) : "memory");
        }
    }

    // Two matrices per thread: slot a = tid, slot b = TPB + tid.
    {
        const int ia = tid;
        const int ib = TPB + tid;
        float4 a0 = s_in[3 * ia + 0], a1 = s_in[3 * ia + 1], a2 = s_in[3 * ia + 2];
        float4 b0 = s_in[3 * ib + 0], b1 = s_in[3 * ib + 1], b2 = s_in[3 * ib + 2];

        u64 A[9] = {pk(a0.x, b0.x), pk(a0.y, b0.y), pk(a0.z, b0.z),
                    pk(a1.x, b1.x), pk(a1.y, b1.y), pk(a1.z, b1.z),
                    pk(a2.x, b2.x), pk(a2.y, b2.y), pk(a2.z, b2.z)};
        u64 t[3] = {pk(a0.w, b0.w), pk(a1.w, b1.w), pk(a2.w, b2.w)};

        // Coefficients with S = 2^-1 folded in.
        const float f1 = 0.5f;           // S
        const float f2 = 0.125f;         // S^2/2
        const float f3 = 1.0f / 48.0f;   // S^3/6
        const float f4 = 1.0f / 384.0f;  // S^4/24
        const u64 c1 = pk(f1, f1), c2 = pk(f2, f2);
        const u64 c3 = pk(f3, f3), c4 = pk(f4, f4);
        const u64 one = pk(1.0f, 1.0f);

        // Translation chain (deg-3 phi1; A^3 t term ~1e-6 aggregate, dropped):
        // u = c1*t + c2*At + c3*A^2 t
        u64 w1[3], w2[3], u[3];
        mv3p(A, t, w1);
        mv3p(A, w1, w2);
#pragma unroll
        for (int j = 0; j < 3; j++)
            u[j] = ffma2(t[j], c1, ffma2(w1[j], c2, fmul2(w2[j], c3)));

        // B = A^2
        u64 B[9];
        mm33p(A, A, B);

        // C = c3*A + c4*B  (B*C = S^3 A^3/6 + S^4 A^4/24)
        u64 C[9];
#pragma unroll
        for (int j = 0; j < 9; j++) C[j] = ffma2(B[j], c4, fmul2(A[j], c3));

        // E = I + c1*A + c2*B + B*C, row-wise
        u64 E[9];
#pragma unroll
        for (int r = 0; r < 3; r++) {
            const u64 b0r = B[r * 3 + 0], b1r = B[r * 3 + 1], b2r = B[r * 3 + 2];
#pragma unroll
            for (int c = 0; c < 3; c++) {
                u64 g = ffma2(b0r, C[c], ffma2(b1r, C[3 + c], fmul2(b2r, C[6 + c])));
                u64 e = ffma2(A[r * 3 + c], c1, ffma2(B[r * 3 + c], c2, g));
                if (c == r) e = fadd2(e, one);
                E[r * 3 + c] = e;
            }
        }

        // One affine squaring: [E,u] <- [E^2, E u + u]
        u64 F[9], v2[3];
        mm33p(E, E, F);
        mv3p(E, u, v2);
#pragma unroll
        for (int j = 0; j < 3; j++) u[j] = fadd2(v2[j], u[j]);

        // Unpack and write both matrices to smem.
        float ea[12], eb[12];
        upk(F[0], ea[0], eb[0]);   upk(F[1], ea[1], eb[1]);   upk(F[2], ea[2], eb[2]);
        upk(u[0], ea[3], eb[3]);
        upk(F[3], ea[4], eb[4]);   upk(F[4], ea[5], eb[5]);   upk(F[5], ea[6], eb[6]);
        upk(u[1], ea[7], eb[7]);
        upk(F[6], ea[8], eb[8]);   upk(F[7], ea[9], eb[9]);   upk(F[8], ea[10], eb[10]);
        upk(u[2], ea[11], eb[11]);

        s_out[3 * ia + 0] = make_float4(ea[0], ea[1], ea[2], ea[3]);
        s_out[3 * ia + 1] = make_float4(ea[4], ea[5], ea[6], ea[7]);
        s_out[3 * ia + 2] = make_float4(ea[8], ea[9], ea[10], ea[11]);
        s_out[3 * ib + 0] = make_float4(eb[0], eb[1], eb[2], eb[3]);
        s_out[3 * ib + 1] = make_float4(eb[4], eb[5], eb[6], eb[7]);
        s_out[3 * ib + 2] = make_float4(eb[8], eb[9], eb[10], eb[11]);
    }

    // Order generic-proxy smem writes before async-proxy TMA read.
    asm volatile("fence.proxy.async.shared::cta;" ::: "memory");
    __syncthreads();

    if (tid == 0) {
        asm volatile(
            "cp.async.bulk.global.shared::cta.bulk_group [%0], [%1], %2;"
            :: "l"(out + (size_t)base * 3), "r"(sout_a), "r"(bytes)
            : "memory");
        asm volatile("cp.async.bulk.commit_group;" ::: "memory");
        asm volatile("cp.async.bulk.wait_group 0;" ::: "memory");
    }
}

extern "C" void kernel_launch(void* const* d_in, const int* in_sizes, int n_in,
                              void* d_out, int out_size) {
    const float* vec = (const float*)d_in[0];
    float* outp = (float*)d_out;
    int n = in_sizes[0] / 12;

    int blocks = (n + MPB - 1) / MPB;
    expaff_kernel<<<blocks, TPB>>>((const float4*)vec, (float4*)outp, n);
}

// round 10
// speedup vs baseline: 1.1636x; 1.1636x over previous
#include <cuda_runtime.h>
#include <cuda_bf16.h>
#include <cstdint>

// Batched exp of log-affine matrices (ndims=3), B=1e6.
// R10: software-pipelined double-chunk blocks. Each block handles 2 chunks
// of 256 matrices; BOTH TMA bulk loads are issued at block start, so chunk1's
// memory latency hides behind chunk0's compute, and chunk0's bulk store
// overlaps chunk1's compute (wait_group.read before s_out reuse).
// Math: packed f32x2, two matrices/thread, s=1 scaling, deg-4 Taylor
// (Paterson-Stockmeyer), deg-3 phi1 chain, one affine squaring.
// rel_err ~4e-6 << 1e-3 bar (measured in R9).

#define TPB 128
#define CHUNK (2 * TPB)        // 256 matrices per chunk
#define BLKM (2 * CHUNK)       // 512 matrices per block

typedef unsigned long long u64;

__device__ __forceinline__ uint32_t smem_u32(const void* p) {
    return (uint32_t)__cvta_generic_to_shared(p);
}

__device__ __forceinline__ u64 pk(float lo, float hi) {
    u64 r;
    asm("mov.b64 %0, {%1, %2};" : "=l"(r) : "f"(lo), "f"(hi));
    return r;
}
__device__ __forceinline__ void upk(u64 v, float& lo, float& hi) {
    asm("mov.b64 {%0, %1}, %2;" : "=f"(lo), "=f"(hi) : "l"(v));
}
__device__ __forceinline__ u64 ffma2(u64 a, u64 b, u64 c) {
    u64 d;
    asm("fma.rn.f32x2 %0, %1, %2, %3;" : "=l"(d) : "l"(a), "l"(b), "l"(c));
    return d;
}
__device__ __forceinline__ u64 fmul2(u64 a, u64 b) {
    u64 d;
    asm("mul.rn.f32x2 %0, %1, %2;" : "=l"(d) : "l"(a), "l"(b));
    return d;
}
__device__ __forceinline__ u64 fadd2(u64 a, u64 b) {
    u64 d;
    asm("add.rn.f32x2 %0, %1, %2;" : "=l"(d) : "l"(a), "l"(b));
    return d;
}

__device__ __forceinline__ void mm33p(const u64* __restrict__ X,
                                      const u64* __restrict__ Y,
                                      u64* __restrict__ Z) {
#pragma unroll
    for (int r = 0; r < 3; r++) {
        const u64 x0 = X[r * 3 + 0], x1 = X[r * 3 + 1], x2 = X[r * 3 + 2];
#pragma unroll
        for (int c = 0; c < 3; c++)
            Z[r * 3 + c] = ffma2(x0, Y[c], ffma2(x1, Y[3 + c], fmul2(x2, Y[6 + c])));
    }
}

__device__ __forceinline__ void mv3p(const u64* __restrict__ X,
                                     const u64* __restrict__ v,
                                     u64* __restrict__ w) {
#pragma unroll
    for (int r = 0; r < 3; r++)
        w[r] = ffma2(X[r * 3 + 0], v[0],
               ffma2(X[r * 3 + 1], v[1], fmul2(X[r * 3 + 2], v[2])));
}

// Process one chunk resident in s_in -> s_out. nblk = valid matrices (<= CHUNK).
__device__ __forceinline__ void process_chunk(const float4* __restrict__ s_in,
                                              float4* __restrict__ s_out,
                                              int tid, int nblk) {
    const bool full = (nblk == CHUNK);
    const int ia = tid;
    const int ib = TPB + tid;

    float4 a0, a1, a2, b0, b1, b2;
    if (full) {
        a0 = s_in[3 * ia + 0]; a1 = s_in[3 * ia + 1]; a2 = s_in[3 * ia + 2];
        b0 = s_in[3 * ib + 0]; b1 = s_in[3 * ib + 1]; b2 = s_in[3 * ib + 2];
    } else {
        float4 z = make_float4(0.f, 0.f, 0.f, 0.f);
        a0 = a1 = a2 = b0 = b1 = b2 = z;
        if (ia < nblk) { a0 = s_in[3 * ia + 0]; a1 = s_in[3 * ia + 1]; a2 = s_in[3 * ia + 2]; }
        if (ib < nblk) { b0 = s_in[3 * ib + 0]; b1 = s_in[3 * ib + 1]; b2 = s_in[3 * ib + 2]; }
    }

    u64 A[9] = {pk(a0.x, b0.x), pk(a0.y, b0.y), pk(a0.z, b0.z),
                pk(a1.x, b1.x), pk(a1.y, b1.y), pk(a1.z, b1.z),
                pk(a2.x, b2.x), pk(a2.y, b2.y), pk(a2.z, b2.z)};
    u64 t[3] = {pk(a0.w, b0.w), pk(a1.w, b1.w), pk(a2.w, b2.w)};

    // S = 2^-1 folded coefficients
    const float f1 = 0.5f;           // S
    const float f2 = 0.125f;         // S^2/2
    const float f3 = 1.0f / 48.0f;   // S^3/6
    const float f4 = 1.0f / 384.0f;  // S^4/24
    const u64 c1 = pk(f1, f1), c2 = pk(f2, f2);
    const u64 c3 = pk(f3, f3), c4 = pk(f4, f4);
    const u64 one = pk(1.0f, 1.0f);

    // phi1 chain (deg-3): u = c1*t + c2*A t + c3*A^2 t
    u64 w1[3], w2[3], u[3];
    mv3p(A, t, w1);
    mv3p(A, w1, w2);
#pragma unroll
    for (int j = 0; j < 3; j++)
        u[j] = ffma2(t[j], c1, ffma2(w1[j], c2, fmul2(w2[j], c3)));

    // B = A^2
    u64 B[9];
    mm33p(A, A, B);

    // C = c3*A + c4*B  (B*C = S^3 A^3/6 + S^4 A^4/24)
    u64 C[9];
#pragma unroll
    for (int j = 0; j < 9; j++) C[j] = ffma2(B[j], c4, fmul2(A[j], c3));

    // E = I + c1*A + c2*B + B*C, row-wise
    u64 E[9];
#pragma unroll
    for (int r = 0; r < 3; r++) {
        const u64 b0r = B[r * 3 + 0], b1r = B[r * 3 + 1], b2r = B[r * 3 + 2];
#pragma unroll
        for (int c = 0; c < 3; c++) {
            u64 g = ffma2(b0r, C[c], ffma2(b1r, C[3 + c], fmul2(b2r, C[6 + c])));
            u64 e = ffma2(A[r * 3 + c], c1, ffma2(B[r * 3 + c], c2, g));
            if (c == r) e = fadd2(e, one);
            E[r * 3 + c] = e;
        }
    }

    // One affine squaring: [E,u] -> [E^2, E u + u]
    u64 F[9], v2[3];
    mm33p(E, E, F);
    mv3p(E, u, v2);
#pragma unroll
    for (int j = 0; j < 3; j++) u[j] = fadd2(v2[j], u[j]);

    float ea[12], eb[12];
    upk(F[0], ea[0], eb[0]);   upk(F[1], ea[1], eb[1]);   upk(F[2], ea[2], eb[2]);
    upk(u[0], ea[3], eb[3]);
    upk(F[3], ea[4], eb[4]);   upk(F[4], ea[5], eb[5]);   upk(F[5], ea[6], eb[6]);
    upk(u[1], ea[7], eb[7]);
    upk(F[6], ea[8], eb[8]);   upk(F[7], ea[9], eb[9]);   upk(F[8], ea[10], eb[10]);
    upk(u[2], ea[11], eb[11]);

    if (full || ia < nblk) {
        s_out[3 * ia + 0] = make_float4(ea[0], ea[1], ea[2], ea[3]);
        s_out[3 * ia + 1] = make_float4(ea[4], ea[5], ea[6], ea[7]);
        s_out[3 * ia + 2] = make_float4(ea[8], ea[9], ea[10], ea[11]);
    }
    if (full || ib < nblk) {
        s_out[3 * ib + 0] = make_float4(eb[0], eb[1], eb[2], eb[3]);
        s_out[3 * ib + 1] = make_float4(eb[4], eb[5], eb[6], eb[7]);
        s_out[3 * ib + 2] = make_float4(eb[8], eb[9], eb[10], eb[11]);
    }
}

__device__ __forceinline__ void mbar_wait0(uint32_t mbar_a) {
    uint32_t done;
    asm volatile(
        "{\n\t.reg .pred p;\n\t"
        "mbarrier.try_wait.parity.acquire.cta.shared::cta.b64 p, [%1], 0;\n\t"
        "selp.b32 %0, 1, 0, p;\n\t}"
        : "=r"(done) : "r"(mbar_a) : "memory");
    if (!done) {
        asm volatile(
            "{\n\t.reg .pred P1;\n\t"
            "WL_%=:\n\t"
            "mbarrier.try_wait.parity.acquire.cta.shared::cta.b64 P1, [%0], 0, 0x989680;\n\t"
            "@P1 bra.uni WD_%=;\n\t"
            "bra.uni WL_%=;\n\t"
            "WD_%=:\n\t}"
            :: "r"(mbar_a) : "memory");
    }
}

__global__ void __launch_bounds__(TPB)
expaff_kernel(const float4* __restrict__ in, float4* __restrict__ out, int n) {
    __shared__ alignas(16) float4 s_in0[CHUNK * 3];   // 12 KB
    __shared__ alignas(16) float4 s_in1[CHUNK * 3];   // 12 KB
    __shared__ alignas(16) float4 s_out[CHUNK * 3];   // 12 KB
    __shared__ alignas(8) unsigned long long mbar[2];

    const int tid = threadIdx.x;
    const int base0 = blockIdx.x * BLKM;
    const int base1 = base0 + CHUNK;
    int nb0 = n - base0; nb0 = nb0 < 0 ? 0 : (nb0 > CHUNK ? CHUNK : nb0);
    int nb1 = n - base1; nb1 = nb1 < 0 ? 0 : (nb1 > CHUNK ? CHUNK : nb1);
    const uint32_t bytes0 = (uint32_t)nb0 * 48u;
    const uint32_t bytes1 = (uint32_t)nb1 * 48u;

    const uint32_t mb0 = smem_u32(&mbar[0]);
    const uint32_t mb1 = smem_u32(&mbar[1]);
    const uint32_t sin0_a = smem_u32(s_in0);
    const uint32_t sin1_a = smem_u32(s_in1);
    const uint32_t sout_a = smem_u32(s_out);

    if (tid == 0) {
        asm volatile("mbarrier.init.shared.b64 [%0], 1;" :: "r"(mb0) : "memory");
        asm volatile("mbarrier.init.shared.b64 [%0], 1;" :: "r"(mb1) : "memory");
    }
    __syncthreads();

    // Issue BOTH chunk loads immediately (chunk1 latency hides behind chunk0 work)
    if (tid == 0) {
        asm volatile("mbarrier.arrive.expect_tx.shared.b64 _, [%0], %1;"
                     :: "r"(mb0), "r"(bytes0) : "memory");
        asm volatile(
            "cp.async.bulk.shared::cta.global.mbarrier::complete_tx::bytes "
            "[%0], [%1], %2, [%3];"
            :: "r"(sin0_a), "l"(in + (size_t)base0 * 3), "r"(bytes0), "r"(mb0)
            : "memory");
        if (nb1 > 0) {
            asm volatile("mbarrier.arrive.expect_tx.shared.b64 _, [%0], %1;"
                         :: "r"(mb1), "r"(bytes1) : "memory");
            asm volatile(
                "cp.async.bulk.shared::cta.global.mbarrier::complete_tx::bytes "
                "[%0], [%1], %2, [%3];"
                :: "r"(sin1_a), "l"(in + (size_t)base1 * 3), "r"(bytes1), "r"(mb1)
                : "memory");
        }
    }

    // ---- Chunk 0 ----
    mbar_wait0(mb0);
    process_chunk(s_in0, s_out, tid, nb0);

    asm volatile("fence.proxy.async.shared::cta;" ::: "memory");
    __syncthreads();

    if (tid == 0) {
        asm volatile(
            "cp.async.bulk.global.shared::cta.bulk_group [%0], [%1], %2;"
            :: "l"(out + (size_t)base0 * 3), "r"(sout_a), "r"(bytes0)
            : "memory");
        asm volatile("cp.async.bulk.commit_group;" ::: "memory");
    }

    // ---- Chunk 1 (compute overlaps chunk0's bulk store) ----
    if (nb1 > 0) {
        mbar_wait0(mb1);

        // s_out reuse: ensure chunk0's store has finished READING smem.
        if (tid == 0) {
            asm volatile("cp.async.bulk.wait_group.read 0;" ::: "memory");
        }
        __syncthreads();

        process_chunk(s_in1, s_out, tid, nb1);

        asm volatile("fence.proxy.async.shared::cta;" ::: "memory");
        __syncthreads();

        if (tid == 0) {
            asm volatile(
                "cp.async.bulk.global.shared::cta.bulk_group [%0], [%1], %2;"
                :: "l"(out + (size_t)base1 * 3), "r"(sout_a), "r"(bytes1)
                : "memory");
            asm volatile("cp.async.bulk.commit_group;" ::: "memory");
        }
    }

    // Final: smem must stay valid until all bulk stores complete.
    if (tid == 0) {
        asm volatile("cp.async.bulk.wait_group 0;" ::: "memory");
    }
}

extern "C" void kernel_launch(void* const* d_in, const int* in_sizes, int n_in,
                              void* d_out, int out_size) {
    const float* vec = (const float*)d_in[0];
    float* outp = (float*)d_out;
    int n = in_sizes[0] / 12;

    int blocks = (n + BLKM - 1) / BLKM;
    expaff_kernel<<<blocks, TPB>>>((const float4*)vec, (float4*)outp, n);
}

// round 11
// speedup vs baseline: 1.2500x; 1.0742x over previous
#include <cuda_runtime.h>
#include <cuda_bf16.h>
#include <cstdint>

// Batched exp of log-affine matrices (ndims=3), B=1e6.
// R11: persistent CTAs + 3-stage in-place TMA ring. Grid = 148*6 CTAs,
// each grid-strides over chunks of 256 matrices. Loads for stages j+1,j+2
// stay in flight while stage j computes; stores drain asynchronously.
// In-place buffers (each thread owns its 6 float4 slots) keep smem at
// 36 KB -> 6 CTAs/SM. Math: packed f32x2, two matrices/thread, s=1
// scaling, deg-4 Taylor (Paterson-Stockmeyer), deg-3 phi1 chain, one
// affine squaring. rel_err ~4e-6 << 1e-3 bar (measured R9/R10).

#define TPB 128
#define CHUNK 256          // matrices per chunk (2 per thread)
#define NSTAGE 3
#define NSM 148
#define CTAS_PER_SM 6

typedef unsigned long long u64;

__device__ __forceinline__ uint32_t smem_u32(const void* p) {
    return (uint32_t)__cvta_generic_to_shared(p);
}

__device__ __forceinline__ u64 pk(float lo, float hi) {
    u64 r;
    asm("mov.b64 %0, {%1, %2};" : "=l"(r) : "f"(lo), "f"(hi));
    return r;
}
__device__ __forceinline__ void upk(u64 v, float& lo, float& hi) {
    asm("mov.b64 {%0, %1}, %2;" : "=f"(lo), "=f"(hi) : "l"(v));
}
__device__ __forceinline__ u64 ffma2(u64 a, u64 b, u64 c) {
    u64 d;
    asm("fma.rn.f32x2 %0, %1, %2, %3;" : "=l"(d) : "l"(a), "l"(b), "l"(c));
    return d;
}
__device__ __forceinline__ u64 fmul2(u64 a, u64 b) {
    u64 d;
    asm("mul.rn.f32x2 %0, %1, %2;" : "=l"(d) : "l"(a), "l"(b));
    return d;
}
__device__ __forceinline__ u64 fadd2(u64 a, u64 b) {
    u64 d;
    asm("add.rn.f32x2 %0, %1, %2;" : "=l"(d) : "l"(a), "l"(b));
    return d;
}

__device__ __forceinline__ void mm33p(const u64* __restrict__ X,
                                      const u64* __restrict__ Y,
                                      u64* __restrict__ Z) {
#pragma unroll
    for (int r = 0; r < 3; r++) {
        const u64 x0 = X[r * 3 + 0], x1 = X[r * 3 + 1], x2 = X[r * 3 + 2];
#pragma unroll
        for (int c = 0; c < 3; c++)
            Z[r * 3 + c] = ffma2(x0, Y[c], ffma2(x1, Y[3 + c], fmul2(x2, Y[6 + c])));
    }
}

__device__ __forceinline__ void mv3p(const u64* __restrict__ X,
                                     const u64* __restrict__ v,
                                     u64* __restrict__ w) {
#pragma unroll
    for (int r = 0; r < 3; r++)
        w[r] = ffma2(X[r * 3 + 0], v[0],
               ffma2(X[r * 3 + 1], v[1], fmul2(X[r * 3 + 2], v[2])));
}

// Compute one chunk in place: read own slots from buf, write results back.
__device__ __forceinline__ void process_chunk(float4* __restrict__ buf,
                                              int tid, int nblk) {
    const bool full = (nblk == CHUNK);
    const int ia = tid;
    const int ib = TPB + tid;

    float4 a0, a1, a2, b0, b1, b2;
    if (full) {
        a0 = buf[3 * ia + 0]; a1 = buf[3 * ia + 1]; a2 = buf[3 * ia + 2];
        b0 = buf[3 * ib + 0]; b1 = buf[3 * ib + 1]; b2 = buf[3 * ib + 2];
    } else {
        float4 z = make_float4(0.f, 0.f, 0.f, 0.f);
        a0 = a1 = a2 = b0 = b1 = b2 = z;
        if (ia < nblk) { a0 = buf[3 * ia + 0]; a1 = buf[3 * ia + 1]; a2 = buf[3 * ia + 2]; }
        if (ib < nblk) { b0 = buf[3 * ib + 0]; b1 = buf[3 * ib + 1]; b2 = buf[3 * ib + 2]; }
    }

    u64 A[9] = {pk(a0.x, b0.x), pk(a0.y, b0.y), pk(a0.z, b0.z),
                pk(a1.x, b1.x), pk(a1.y, b1.y), pk(a1.z, b1.z),
                pk(a2.x, b2.x), pk(a2.y, b2.y), pk(a2.z, b2.z)};
    u64 t[3] = {pk(a0.w, b0.w), pk(a1.w, b1.w), pk(a2.w, b2.w)};

    // S = 2^-1 folded coefficients
    const float f1 = 0.5f;           // S
    const float f2 = 0.125f;         // S^2/2
    const float f3 = 1.0f / 48.0f;   // S^3/6
    const float f4 = 1.0f / 384.0f;  // S^4/24
    const u64 c1 = pk(f1, f1), c2 = pk(f2, f2);
    const u64 c3 = pk(f3, f3), c4 = pk(f4, f4);
    const u64 one = pk(1.0f, 1.0f);

    // phi1 chain (deg-3): u = c1*t + c2*A t + c3*A^2 t
    u64 w1[3], w2[3], u[3];
    mv3p(A, t, w1);
    mv3p(A, w1, w2);
#pragma unroll
    for (int j = 0; j < 3; j++)
        u[j] = ffma2(t[j], c1, ffma2(w1[j], c2, fmul2(w2[j], c3)));

    // B = A^2
    u64 B[9];
    mm33p(A, A, B);

    // C = c3*A + c4*B  (B*C = S^3 A^3/6 + S^4 A^4/24)
    u64 C[9];
#pragma unroll
    for (int j = 0; j < 9; j++) C[j] = ffma2(B[j], c4, fmul2(A[j], c3));

    // E = I + c1*A + c2*B + B*C, row-wise
    u64 E[9];
#pragma unroll
    for (int r = 0; r < 3; r++) {
        const u64 b0r = B[r * 3 + 0], b1r = B[r * 3 + 1], b2r = B[r * 3 + 2];
#pragma unroll
        for (int c = 0; c < 3; c++) {
            u64 g = ffma2(b0r, C[c], ffma2(b1r, C[3 + c], fmul2(b2r, C[6 + c])));
            u64 e = ffma2(A[r * 3 + c], c1, ffma2(B[r * 3 + c], c2, g));
            if (c == r) e = fadd2(e, one);
            E[r * 3 + c] = e;
        }
    }

    // One affine squaring: [E,u] -> [E^2, E u + u]
    u64 F[9], v2[3];
    mm33p(E, E, F);
    mv3p(E, u, v2);
#pragma unroll
    for (int j = 0; j < 3; j++) u[j] = fadd2(v2[j], u[j]);

    float ea[12], eb[12];
    upk(F[0], ea[0], eb[0]);   upk(F[1], ea[1], eb[1]);   upk(F[2], ea[2], eb[2]);
    upk(u[0], ea[3], eb[3]);
    upk(F[3], ea[4], eb[4]);   upk(F[4], ea[5], eb[5]);   upk(F[5], ea[6], eb[6]);
    upk(u[1], ea[7], eb[7]);
    upk(F[6], ea[8], eb[8]);   upk(F[7], ea[9], eb[9]);   upk(F[8], ea[10], eb[10]);
    upk(u[2], ea[11], eb[11]);

    if (full || ia < nblk) {
        buf[3 * ia + 0] = make_float4(ea[0], ea[1], ea[2], ea[3]);
        buf[3 * ia + 1] = make_float4(ea[4], ea[5], ea[6], ea[7]);
        buf[3 * ia + 2] = make_float4(ea[8], ea[9], ea[10], ea[11]);
    }
    if (full || ib < nblk) {
        buf[3 * ib + 0] = make_float4(eb[0], eb[1], eb[2], eb[3]);
        buf[3 * ib + 1] = make_float4(eb[4], eb[5], eb[6], eb[7]);
        buf[3 * ib + 2] = make_float4(eb[8], eb[9], eb[10], eb[11]);
    }
}

__device__ __forceinline__ void mbar_wait(uint32_t mbar_a, uint32_t parity) {
    uint32_t done;
    asm volatile(
        "{\n\t.reg .pred p;\n\t"
        "mbarrier.try_wait.parity.acquire.cta.shared::cta.b64 p, [%1], %2;\n\t"
        "selp.b32 %0, 1, 0, p;\n\t}"
        : "=r"(done) : "r"(mbar_a), "r"(parity) : "memory");
    if (!done) {
        asm volatile(
            "{\n\t.reg .pred P1;\n\t"
            "WL_%=:\n\t"
            "mbarrier.try_wait.parity.acquire.cta.shared::cta.b64 P1, [%0], %1, 0x989680;\n\t"
            "@P1 bra.uni WD_%=;\n\t"
            "bra.uni WL_%=;\n\t"
            "WD_%=:\n\t}"
            :: "r"(mbar_a), "r"(parity) : "memory");
    }
}

__global__ void __launch_bounds__(TPB)
expaff_kernel(const float4* __restrict__ in, float4* __restrict__ out,
              int n, int nchunks) {
    __shared__ alignas(16) float4 buf[NSTAGE][CHUNK * 3];   // 3 x 12 KB
    __shared__ alignas(8) unsigned long long mbar[NSTAGE];

    const int tid = threadIdx.x;
    const int bid = blockIdx.x;
    const int G = gridDim.x;

    if (tid == 0) {
#pragma unroll
        for (int s = 0; s < NSTAGE; s++)
            asm volatile("mbarrier.init.shared.b64 [%0], 1;"
                         :: "r"(smem_u32(&mbar[s])) : "memory");
    }
    __syncthreads();

    // Prologue: fill the ring.
    if (tid == 0) {
#pragma unroll
        for (int k = 0; k < NSTAGE; k++) {
            int c = bid + k * G;
            if (c < nchunks) {
                int cbase = c * CHUNK;
                int nb = min(CHUNK, n - cbase);
                uint32_t bytes = (uint32_t)nb * 48u;
                uint32_t mb = smem_u32(&mbar[k]);
                asm volatile("mbarrier.arrive.expect_tx.shared.b64 _, [%0], %1;"
                             :: "r"(mb), "r"(bytes) : "memory");
                asm volatile(
                    "cp.async.bulk.shared::cta.global.mbarrier::complete_tx::bytes "
                    "[%0], [%1], %2, [%3];"
                    :: "r"(smem_u32(&buf[k][0])), "l"(in + (size_t)cbase * 3),
                       "r"(bytes), "r"(mb)
                    : "memory");
            }
        }
    }

    // Main loop over this CTA's chunks.
    for (int j = 0, c = bid; c < nchunks; j++, c += G) {
        const int s = j % NSTAGE;
        const uint32_t parity = (uint32_t)((j / NSTAGE) & 1);
        const int cbase = c * CHUNK;
        const int nb = min(CHUNK, n - cbase);
        const uint32_t bytes = (uint32_t)nb * 48u;
        const uint32_t mb = smem_u32(&mbar[s]);

        mbar_wait(mb, parity);

        process_chunk(&buf[s][0], tid, nb);

        // Order generic-proxy smem writes before async-proxy TMA read.
        asm volatile("fence.proxy.async.shared::cta;" ::: "memory");
        __syncthreads();

        if (tid == 0) {
            asm volatile(
                "cp.async.bulk.global.shared::cta.bulk_group [%0], [%1], %2;"
                :: "l"(out + (size_t)cbase * 3), "r"(smem_u32(&buf[s][0])),
                   "r"(bytes)
                : "memory");
            asm volatile("cp.async.bulk.commit_group;" ::: "memory");

            // Refill this stage with chunk c + NSTAGE*G, if any.
            int cn = c + NSTAGE * G;
            if (cn < nchunks) {
                // All outstanding stores (incl. the one just issued from this
                // buffer) must finish READING smem before the new load lands.
                asm volatile("cp.async.bulk.wait_group.read 0;" ::: "memory");
                int cnbase = cn * CHUNK;
                int nb2 = min(CHUNK, n - cnbase);
                uint32_t bytes2 = (uint32_t)nb2 * 48u;
                asm volatile("mbarrier.arrive.expect_tx.shared.b64 _, [%0], %1;"
                             :: "r"(mb), "r"(bytes2) : "memory");
                asm volatile(
                    "cp.async.bulk.shared::cta.global.mbarrier::complete_tx::bytes "
                    "[%0], [%1], %2, [%3];"
                    :: "r"(smem_u32(&buf[s][0])), "l"(in + (size_t)cnbase * 3),
                       "r"(bytes2), "r"(mb)
                    : "memory");
            }
        }
    }

    // smem must stay valid until all bulk stores complete.
    if (tid == 0) {
        asm volatile("cp.async.bulk.wait_group 0;" ::: "memory");
    }
}

extern "C" void kernel_launch(void* const* d_in, const int* in_sizes, int n_in,
                              void* d_out, int out_size) {
    const float* vec = (const float*)d_in[0];
    float* outp = (float*)d_out;
    int n = in_sizes[0] / 12;
    int nchunks = (n + CHUNK - 1) / CHUNK;

    int grid = NSM * CTAS_PER_SM;
    if (grid > nchunks) grid = nchunks;
    expaff_kernel<<<grid, TPB>>>((const float4*)vec, (float4*)outp, n, nchunks);
}